// round 16
// baseline (speedup 1.0000x reference)
#include <cuda_runtime.h>
#include <cstdint>

#define H 512
#define W 512
#define NB 32

#define SQRT_APPROX(d, a) \
    asm("sqrt.approx.f32 %0, %1;" : "=f"(d) : "f"(a))

// 256-bit load with direct L2 evict_last (valid per ptxas: v8.b32 width).
// One instruction loads 8 contiguous fp32 per lane; warp = 1024B contiguous.
#define LDG8_EL(r, p)                                                          \
    asm("ld.global.nc.L2::evict_last.v8.b32 {%0,%1,%2,%3,%4,%5,%6,%7}, [%8];"  \
        : "=f"((r)[0]), "=f"((r)[1]), "=f"((r)[2]), "=f"((r)[3]),              \
          "=f"((r)[4]), "=f"((r)[5]), "=f"((r)[6]), "=f"((r)[7])               \
        : "l"(p))

// Thread = 8 px of one row. Warp = 256 px (half row). Block = 256 thr = 4
// full rows. Shuffle halo; approx sqrt; __stcs float4 stores (contiguous
// full-row bursts). grid = (H/4, NB).
__global__ __launch_bounds__(256) void sqdiff_mag_kernel(
    const float* __restrict__ x, float* __restrict__ out)
{
    int lane  = threadIdx.x & 31;
    int warp  = threadIdx.x >> 5;            // 0..7
    int strip = warp & 1;                    // 0..1 half-row
    int h     = (blockIdx.x << 2) + (warp >> 1);
    int n     = blockIdx.y;

    int wbase = strip << 8;                  // 0 or 256
    int w     = wbase + (lane << 3);

    const size_t plane = (size_t)H * W;
    const float* g = x + ((size_t)n * 3 + 1) * plane;   // channel 1

    // r[j][0] = left halo, r[j][1..8] = 8 px, r[j][9] = right halo
    float r[3][10];

    #define LOAD_ROW(j, hh)                                                    \
    {                                                                          \
        const float* p = g + (size_t)(hh) * W + w;                             \
        LDG8_EL(&r[j][1], p);                                                  \
        float lft = __shfl_up_sync(0xffffffffu, r[j][8], 1);                   \
        float rgt = __shfl_down_sync(0xffffffffu, r[j][1], 1);                 \
        if (lane == 0)  lft = (wbase > 0)       ? __ldg(p - 1) : 0.0f;         \
        if (lane == 31) rgt = (wbase + 256 < W) ? __ldg(p + 8) : 0.0f;         \
        r[j][0] = lft; r[j][9] = rgt;                                          \
    }

    LOAD_ROW(1, h)
    if (h > 0) {
        LOAD_ROW(0, h - 1)
    } else {
        #pragma unroll
        for (int i = 0; i < 10; i++) r[0][i] = 0.0f;
    }
    if (h + 1 < H) {
        LOAD_ROW(2, h + 1)
    } else {
        #pragma unroll
        for (int i = 0; i < 10; i++) r[2][i] = 0.0f;
    }
    #undef LOAD_ROW

    float4 resA, resB;
    float* ra = reinterpret_cast<float*>(&resA);
    float* rb = reinterpret_cast<float*>(&resB);

    #pragma unroll
    for (int i = 0; i < 8; i++) {
        float c  = r[1][i + 1];
        float d0 = c - r[1][i + 2];
        float d1 = c - r[1][i];
        float d2 = c - r[2][i + 1];
        float d3 = c - r[0][i + 1];
        float d4 = c - r[2][i + 2];
        float d5 = c - r[2][i];
        float d6 = c - r[0][i + 2];
        float d7 = c - r[0][i];
        float s = d0 * d0;
        s = fmaf(d1, d1, s);
        s = fmaf(d2, d2, s);
        s = fmaf(d3, d3, s);
        s = fmaf(d4, d4, s);
        s = fmaf(d5, d5, s);
        s = fmaf(d6, d6, s);
        s = fmaf(d7, d7, s);
        float m;
        SQRT_APPROX(m, s);
        if (i < 4) ra[i] = m; else rb[i - 4] = m;
    }

    float* ob = out + (size_t)n * 3 * plane + (size_t)h * W + w;
    __stcs(reinterpret_cast<float4*>(ob),                 resA);
    __stcs(reinterpret_cast<float4*>(ob + 4),             resB);
    __stcs(reinterpret_cast<float4*>(ob + plane),         resA);
    __stcs(reinterpret_cast<float4*>(ob + plane + 4),     resB);
    __stcs(reinterpret_cast<float4*>(ob + 2 * plane),     resA);
    __stcs(reinterpret_cast<float4*>(ob + 2 * plane + 4), resB);
}

extern "C" void kernel_launch(void* const* d_in, const int* in_sizes, int n_in,
                              void* d_out, int out_size)
{
    const float* x = (const float*)d_in[0];
    float* out = (float*)d_out;

    dim3 grid(H / 4, NB);   // 128 x 32 = 4096 CTAs of 256 threads
    sqdiff_mag_kernel<<<grid, 256>>>(x, out);
}

// round 17
// speedup vs baseline: 1.4451x; 1.4451x over previous
#include <cuda_runtime.h>
#include <cstdint>

#define H 512
#define W 512
#define NB 32

#define SQRT_APPROX(d, a) \
    asm("sqrt.approx.f32 %0, %1;" : "=f"(d) : "f"(a))

// Per-access L2 policy: evict_last for the 32MB input (keep resident) while
// the 96MB output streams out via evict-first __stcs. 16B loads use the
// createpolicy + L2::cache_hint form.
#define LDG4_EL(v, p, pol)                                                     \
    asm("ld.global.nc.L2::cache_hint.v4.f32 {%0,%1,%2,%3}, [%4], %5;"          \
        : "=f"((v).x), "=f"((v).y), "=f"((v).z), "=f"((v).w)                   \
        : "l"(p), "l"(pol))

// Champion configuration (R15, 23.0us):
//  - block = 256 threads = 2 full rows; thread = 4 contiguous px (float4)
//  - horizontal halo via warp shuffle (edge lanes: 1 scalar __ldg)
//  - sqrt.approx (MUFU) instead of IEEE sqrt expansion
//  - input loads L2::evict_last, output stores evict-first (__stcs)
//  - grid = (H/2, NB)
__global__ __launch_bounds__(256) void sqdiff_mag_kernel(
    const float* __restrict__ x, float* __restrict__ out)
{
    uint64_t pol;
    asm("createpolicy.fractional.L2::evict_last.b64 %0, 1.0;" : "=l"(pol));

    int lane = threadIdx.x & 31;
    int wg   = threadIdx.x & 127;                     // float4 group in row
    int h    = (blockIdx.x << 1) + (threadIdx.x >> 7);
    int n    = blockIdx.y;

    int w     = wg << 2;
    int wbase = w & ~127;                             // warp's 128-px strip

    const size_t plane = (size_t)H * W;
    const float* g = x + ((size_t)n * 3 + 1) * plane; // channel 1

    float rm[6], rc[6], rp[6];

    #define LOAD_ROW(dst, hh)                                                  \
    {                                                                          \
        const float* p = g + (size_t)(hh) * W + w;                             \
        float4 v;                                                              \
        LDG4_EL(v, p, pol);                                                    \
        dst[1] = v.x; dst[2] = v.y; dst[3] = v.z; dst[4] = v.w;                \
        float lft = __shfl_up_sync(0xffffffffu, v.w, 1);                       \
        float rgt = __shfl_down_sync(0xffffffffu, v.x, 1);                     \
        if (lane == 0)  lft = (wbase > 0)       ? __ldg(p - 1) : 0.0f;         \
        if (lane == 31) rgt = (wbase + 128 < W) ? __ldg(p + 4) : 0.0f;         \
        dst[0] = lft; dst[5] = rgt;                                            \
    }

    LOAD_ROW(rc, h)
    if (h > 0) {
        LOAD_ROW(rm, h - 1)
    } else {
        #pragma unroll
        for (int i = 0; i < 6; i++) rm[i] = 0.0f;
    }
    if (h + 1 < H) {
        LOAD_ROW(rp, h + 1)
    } else {
        #pragma unroll
        for (int i = 0; i < 6; i++) rp[i] = 0.0f;
    }
    #undef LOAD_ROW

    float4 res;
    float* resp = reinterpret_cast<float*>(&res);

    #pragma unroll
    for (int i = 0; i < 4; i++) {
        float c  = rc[i + 1];
        float d0 = c - rc[i + 2];
        float d1 = c - rc[i];
        float d2 = c - rp[i + 1];
        float d3 = c - rm[i + 1];
        float d4 = c - rp[i + 2];
        float d5 = c - rp[i];
        float d6 = c - rm[i + 2];
        float d7 = c - rm[i];
        float s = d0 * d0;
        s = fmaf(d1, d1, s);
        s = fmaf(d2, d2, s);
        s = fmaf(d3, d3, s);
        s = fmaf(d4, d4, s);
        s = fmaf(d5, d5, s);
        s = fmaf(d6, d6, s);
        s = fmaf(d7, d7, s);
        SQRT_APPROX(resp[i], s);
    }

    float* ob = out + (size_t)n * 3 * plane + (size_t)h * W + w;
    __stcs(reinterpret_cast<float4*>(ob),             res);
    __stcs(reinterpret_cast<float4*>(ob + plane),     res);
    __stcs(reinterpret_cast<float4*>(ob + 2 * plane), res);
}

extern "C" void kernel_launch(void* const* d_in, const int* in_sizes, int n_in,
                              void* d_out, int out_size)
{
    const float* x = (const float*)d_in[0];
    float* out = (float*)d_out;

    dim3 grid(H / 2, NB);     // 256 x 32 blocks of 256 threads
    sqdiff_mag_kernel<<<grid, 256>>>(x, out);
}